// round 7
// baseline (speedup 1.0000x reference)
#include <cuda_runtime.h>
#include <cuda_bf16.h>
#include <cstdint>

// ---------------- problem dims ----------------
#define N_ROWS 32768
#define M_CENT 4096
#define D_DIM  32

#define BLOCK     256                    // 8 warps; warp = 2 x m16 tiles = 32 rows
#define ROWS_CTA  256
#define NTILE     128                    // centers per tile (= one split)
#define NSPLIT    32                     // center splits
#define NRB       (N_ROWS / ROWS_CTA)    // 128 row blocks
#define TOTTILES  (NRB * NSPLIT)         // 4096 work tiles
#define NCTAS     444                    // 148 SMs x 3 CTAs -> single wave
#define BSTRIDE   144                    // 128B payload + 16B pad (conflict-free LDSM)

#define SLOT_B    (NTILE * BSTRIDE)      // 18432
#define SLOT_YA   (NTILE * 8)            // 1024
#define SLOT      (SLOT_B + SLOT_YA)     // 19456
#define SMEM_TOT  (2 * SLOT)             // 38912

// ---------------- device scratch ----------------
__device__ __nv_bfloat16 g_B[M_CENT * 64];        // [m][ hi(32) | lo(32) ]
__device__ float2        g_ya[M_CENT];            // { -0.5*||ys||^2 , alpha }
__device__ float         g_part[NSPLIT * N_ROWS]; // partials

// ---------------- helpers ----------------
__device__ __forceinline__ uint32_t smem_u32(const void* p) {
    uint32_t a;
    asm("{ .reg .u64 t; cvta.to.shared.u64 t, %1; cvt.u32.u64 %0, t; }" : "=r"(a) : "l"(p));
    return a;
}
__device__ __forceinline__ float ex2f(float x) {
    float r; asm("ex2.approx.f32 %0, %1;" : "=f"(r) : "f"(x)); return r;
}
__device__ __forceinline__ void cp16(uint32_t dst, const void* src) {
    asm volatile("cp.async.cg.shared.global [%0], [%1], 16;" :: "r"(dst), "l"(src));
}
__device__ __forceinline__ void cp_commit() {
    asm volatile("cp.async.commit_group;" ::: "memory");
}
template <int N>
__device__ __forceinline__ void cp_wait() {
    asm volatile("cp.async.wait_group %0;" :: "n"(N) : "memory");
}
__device__ __forceinline__ void ldmx4(uint32_t* r, uint32_t addr) {
    asm volatile("ldmatrix.sync.aligned.m8n8.x4.shared.b16 {%0,%1,%2,%3}, [%4];"
                 : "=r"(r[0]), "=r"(r[1]), "=r"(r[2]), "=r"(r[3]) : "r"(addr));
}
__device__ __forceinline__ void mma_bf16(float& d0, float& d1, float& d2, float& d3,
                                         uint32_t a0, uint32_t a1, uint32_t a2, uint32_t a3,
                                         uint32_t b0, uint32_t b1) {
    asm volatile(
        "mma.sync.aligned.m16n8k16.row.col.f32.bf16.bf16.f32 "
        "{%0,%1,%2,%3}, {%4,%5,%6,%7}, {%8,%9}, {%0,%1,%2,%3};"
        : "+f"(d0), "+f"(d1), "+f"(d2), "+f"(d3)
        : "r"(a0), "r"(a1), "r"(a2), "r"(a3), "r"(b0), "r"(b1));
}
__device__ __forceinline__ uint32_t pack_bf2(float a0, float a1) {
    __nv_bfloat162 t(__float2bfloat16(a0), __float2bfloat16(a1));
    return *reinterpret_cast<uint32_t*>(&t);
}

// ---------------- prep: warp per center ----------------
__global__ void prep_kernel(const float* __restrict__ centers,
                            const float* __restrict__ alphas,
                            const float* __restrict__ sigma) {
    const int m  = (blockIdx.x * blockDim.x + threadIdx.x) >> 5;
    const int ln = threadIdx.x & 31;
    if (m >= M_CENT) return;
    const float g = sigma[0];
    const float c = sqrtf(1.44269504088896340736f / (g * g));   // sqrt(log2e)/g
    float v = centers[m * D_DIM + ln] * c;
    __nv_bfloat16 hi = __float2bfloat16(v);
    __nv_bfloat16 lo = __float2bfloat16(v - __bfloat162float(hi));
    g_B[m * 64 + ln]      = hi;
    g_B[m * 64 + 32 + ln] = lo;
    float y2 = v * v;
#pragma unroll
    for (int o = 16; o; o >>= 1) y2 += __shfl_xor_sync(0xFFFFFFFFu, y2, o);
    if (ln == 0) g_ya[m] = make_float2(-0.5f * y2, alphas[m]);
}

// ---------------- B tile loader: tile T -> ring slot ----------------
__device__ __forceinline__ void load_btile(uint32_t sb, int slot, int T, int tid) {
    const int split = T & (NSPLIT - 1);
    const char* src = reinterpret_cast<const char*>(g_B) + (size_t)split * NTILE * 128;
    const uint32_t bd = sb + slot * SLOT;
#pragma unroll
    for (int i = 0; i < 4; i++) {
        int idx = tid + i * BLOCK;          // 0..1023 16B chunks (8 per center)
        int cc = idx >> 3, rr = idx & 7;
        cp16(bd + cc * BSTRIDE + rr * 16, src + idx * 16);
    }
    if (tid < 64) {
        const char* ys = reinterpret_cast<const char*>(g_ya + split * NTILE);
        cp16(bd + SLOT_B + tid * 16, ys + tid * 16);
    }
}

// ---------------- A-fragment builder: one m16 tile from global X ----------------
__device__ __forceinline__ void build_afrag(const float* __restrict__ X, int rowA, int rowB,
                                            int qid, float c, uint32_t af[4][4],
                                            float& exA, float& exB) {
    const float* r0p = X + (size_t)rowA * D_DIM + qid * 2;
    const float* r1p = X + (size_t)rowB * D_DIM + qid * 2;
    float s0 = 0.f, s1 = 0.f;
#pragma unroll
    for (int j = 0; j < 4; j++) {                 // cols 2qid + 8j
        float2 v0 = *reinterpret_cast<const float2*>(r0p + j * 8);
        float2 v1 = *reinterpret_cast<const float2*>(r1p + j * 8);
        v0.x *= c; v0.y *= c; v1.x *= c; v1.y *= c;
        s0 += v0.x * v0.x + v0.y * v0.y;
        s1 += v1.x * v1.x + v1.y * v1.y;
        const int s = j >> 1;
        const int h = (j & 1) << 1;
        float h0x = __bfloat162float(__float2bfloat16(v0.x));
        float h0y = __bfloat162float(__float2bfloat16(v0.y));
        float h1x = __bfloat162float(__float2bfloat16(v1.x));
        float h1y = __bfloat162float(__float2bfloat16(v1.y));
        af[s][h + 0] = pack_bf2(v0.x, v0.y);
        af[s][h + 1] = pack_bf2(v1.x, v1.y);
        af[2 + s][h + 0] = pack_bf2(v0.x - h0x, v0.y - h0y);
        af[2 + s][h + 1] = pack_bf2(v1.x - h1x, v1.y - h1y);
    }
    s0 += __shfl_xor_sync(0xFFFFFFFFu, s0, 1);
    s0 += __shfl_xor_sync(0xFFFFFFFFu, s0, 2);
    s1 += __shfl_xor_sync(0xFFFFFFFFu, s1, 1);
    s1 += __shfl_xor_sync(0xFFFFFFFFu, s1, 2);
    exA = ex2f(-0.5f * s0);
    exB = ex2f(-0.5f * s1);
}

// ---------------- main kernel: persistent, 2 A-tiles per warp ----------------
__global__ void __launch_bounds__(BLOCK, 3)
rbf_main(const float* __restrict__ X,
         const float* __restrict__ sigma) {
    extern __shared__ char smem[];
    const uint32_t sb = smem_u32(smem);
    const int tid  = threadIdx.x;
    const int w    = tid >> 5;
    const int ln   = tid & 31;
    const int gID  = ln >> 2;
    const int qid  = ln & 3;
    const int row0 = w * 16 + gID;      // tile-0 CTA-local rows: row0, row0+8
    const int row2 = row0 + 128;        // tile-1 CTA-local rows: row2, row2+8

    const float g = __ldg(sigma);
    const float c = sqrtf(1.44269504088896340736f / (g * g));

    const int cta = blockIdx.x;
    const int loT = (int)(((long long)cta * TOTTILES) / NCTAS);
    const int hiT = (int)(((long long)(cta + 1) * TOTTILES) / NCTAS);
    const int n   = hiT - loT;

    load_btile(sb, 0, loT, tid);
    cp_commit();
    if (n > 1) load_btile(sb, 1, loT + 1, tid);
    cp_commit();

    const uint32_t blane = (uint32_t)((ln & 7) * BSTRIDE + (ln >> 3) * 16);

    uint32_t af0[4][4], af1[4][4];
    float ex0 = 1.f, ex1 = 1.f, ex2v = 1.f, ex3 = 1.f;
    int curRb = -1;

    for (int i = 0; i < n; i++) {
        const int T  = loT + i;
        const int rb = T >> 5;

        cp_wait<1>();
        __syncthreads();

        if (rb != curRb) {
            curRb = rb;
            const int base = rb * ROWS_CTA;
            build_afrag(X, base + row0, base + row0 + 8, qid, c, af0, ex0, ex1);
            build_afrag(X, base + row2, base + row2 + 8, qid, c, af1, ex2v, ex3);
        }

        const uint32_t Bb  = sb + (i & 1) * SLOT + blane;
        const char*    yab = smem + (i & 1) * SLOT + SLOT_B;

        float acc0 = 0.f, acc1 = 0.f, acc2 = 0.f, acc3 = 0.f;
#pragma unroll
        for (int gi = 0; gi < NTILE / 8; gi++) {
            const uint32_t gb = Bb + gi * (8 * BSTRIDE);
            uint32_t p[4], r[4];
            ldmx4(p, gb);          // hi k0-31
            ldmx4(r, gb + 64);     // lo k0-31

            float dA0=0.f,dA1=0.f,dA2=0.f,dA3=0.f;   // tile0 hi-chain
            float dB0=0.f,dB1=0.f,dB2=0.f,dB3=0.f;   // tile0 lo-chain
            float dC0=0.f,dC1=0.f,dC2=0.f,dC3=0.f;   // tile1 hi-chain
            float dD0=0.f,dD1=0.f,dD2=0.f,dD3=0.f;   // tile1 lo-chain
            // x.y ~= xh*yh + xl*yh + xh*yl (K_eff=96); 12 MMAs reuse p,r
            mma_bf16(dA0,dA1,dA2,dA3, af0[0][0],af0[0][1],af0[0][2],af0[0][3], p[0],p[1]);
            mma_bf16(dC0,dC1,dC2,dC3, af1[0][0],af1[0][1],af1[0][2],af1[0][3], p[0],p[1]);
            mma_bf16(dB0,dB1,dB2,dB3, af0[2][0],af0[2][1],af0[2][2],af0[2][3], p[0],p[1]);
            mma_bf16(dD0,dD1,dD2,dD3, af1[2][0],af1[2][1],af1[2][2],af1[2][3], p[0],p[1]);
            mma_bf16(dA0,dA1,dA2,dA3, af0[1][0],af0[1][1],af0[1][2],af0[1][3], p[2],p[3]);
            mma_bf16(dC0,dC1,dC2,dC3, af1[1][0],af1[1][1],af1[1][2],af1[1][3], p[2],p[3]);
            mma_bf16(dB0,dB1,dB2,dB3, af0[3][0],af0[3][1],af0[3][2],af0[3][3], p[2],p[3]);
            mma_bf16(dD0,dD1,dD2,dD3, af1[3][0],af1[3][1],af1[3][2],af1[3][3], p[2],p[3]);
            mma_bf16(dA0,dA1,dA2,dA3, af0[0][0],af0[0][1],af0[0][2],af0[0][3], r[0],r[1]);
            mma_bf16(dC0,dC1,dC2,dC3, af1[0][0],af1[0][1],af1[0][2],af1[0][3], r[0],r[1]);
            mma_bf16(dB0,dB1,dB2,dB3, af0[1][0],af0[1][1],af0[1][2],af0[1][3], r[2],r[3]);
            mma_bf16(dD0,dD1,dD2,dD3, af1[1][0],af1[1][1],af1[1][2],af1[1][3], r[2],r[3]);

            float4 ya = *reinterpret_cast<const float4*>(yab + gi * 64 + qid * 16);
            acc0 = fmaf(ex2f(dA0 + dB0 + ya.x), ya.y, acc0);
            acc0 = fmaf(ex2f(dA1 + dB1 + ya.z), ya.w, acc0);
            acc1 = fmaf(ex2f(dA2 + dB2 + ya.x), ya.y, acc1);
            acc1 = fmaf(ex2f(dA3 + dB3 + ya.z), ya.w, acc1);
            acc2 = fmaf(ex2f(dC0 + dD0 + ya.x), ya.y, acc2);
            acc2 = fmaf(ex2f(dC1 + dD1 + ya.z), ya.w, acc2);
            acc3 = fmaf(ex2f(dC2 + dD2 + ya.x), ya.y, acc3);
            acc3 = fmaf(ex2f(dC3 + dD3 + ya.z), ya.w, acc3);
        }

        __syncthreads();
        if (i + 2 < n) load_btile(sb, i & 1, T + 2, tid);
        cp_commit();

        acc0 += __shfl_xor_sync(0xFFFFFFFFu, acc0, 1);
        acc0 += __shfl_xor_sync(0xFFFFFFFFu, acc0, 2);
        acc1 += __shfl_xor_sync(0xFFFFFFFFu, acc1, 1);
        acc1 += __shfl_xor_sync(0xFFFFFFFFu, acc1, 2);
        acc2 += __shfl_xor_sync(0xFFFFFFFFu, acc2, 1);
        acc2 += __shfl_xor_sync(0xFFFFFFFFu, acc2, 2);
        acc3 += __shfl_xor_sync(0xFFFFFFFFu, acc3, 1);
        acc3 += __shfl_xor_sync(0xFFFFFFFFu, acc3, 2);
        if (qid == 0) {
            float* dst = g_part + (size_t)(T & (NSPLIT - 1)) * N_ROWS + rb * ROWS_CTA;
            dst[row0]      = acc0 * ex0;
            dst[row0 + 8]  = acc1 * ex1;
            dst[row2]      = acc2 * ex2v;
            dst[row2 + 8]  = acc3 * ex3;
        }
    }
}

// ---------------- final reduce over 32 splits ----------------
__global__ void reduce_kernel(float* __restrict__ out) {
    const int nidx = blockIdx.x * blockDim.x + threadIdx.x;
    float s = 0.f;
#pragma unroll
    for (int i = 0; i < NSPLIT; i++) s += g_part[(size_t)i * N_ROWS + nidx];
    out[nidx] = s;
}

// ---------------- launch ----------------
extern "C" void kernel_launch(void* const* d_in, const int* in_sizes, int n_in,
                              void* d_out, int out_size) {
    const float* X       = (const float*)d_in[0];
    const float* centers = (const float*)d_in[1];
    const float* alphas  = (const float*)d_in[2];
    const float* sigma   = (const float*)d_in[3];
    float* out = (float*)d_out;

    cudaFuncSetAttribute(rbf_main, cudaFuncAttributeMaxDynamicSharedMemorySize, SMEM_TOT);

    prep_kernel<<<M_CENT / 8, 256>>>(centers, alphas, sigma);
    rbf_main<<<NCTAS, BLOCK, SMEM_TOT>>>(X, sigma);
    reduce_kernel<<<N_ROWS / 256, 256>>>(out);
}

// round 8
// speedup vs baseline: 1.0226x; 1.0226x over previous
#include <cuda_runtime.h>
#include <cuda_bf16.h>
#include <cstdint>

// ---------------- problem dims ----------------
#define N_ROWS 32768
#define M_CENT 4096
#define D_DIM  32

#define BLOCK     256                    // 8 warps, warp = 16 rows
#define ROWS_CTA  128
#define NTILE     128                    // centers per tile (= one split)
#define NSPLIT    32                     // center splits
#define NRB       (N_ROWS / ROWS_CTA)    // 256 row blocks
#define TOTTILES  (NRB * NSPLIT)         // 8192 work tiles
#define NCTAS     592                    // 148 SMs x 4 CTAs -> single wave
#define BSTRIDE   144                    // 128B payload + 16B pad (conflict-free LDSM)

#define SLOT_B    (NTILE * BSTRIDE)      // 18432
#define SLOT_YA   (NTILE * 8)            // 1024
#define SLOT      (SLOT_B + SLOT_YA)     // 19456
#define SMEM_TOT  (2 * SLOT)             // 38912 -> 4 CTAs/SM

// ---------------- device scratch ----------------
__device__ __nv_bfloat16 g_B[M_CENT * 64];        // [m][ hi(32) | lo(32) ]
__device__ float2        g_ya[M_CENT];            // { -0.5*||ys||^2 , alpha }
__device__ float         g_part[NSPLIT * N_ROWS]; // partials

// ---------------- helpers ----------------
__device__ __forceinline__ uint32_t smem_u32(const void* p) {
    uint32_t a;
    asm("{ .reg .u64 t; cvta.to.shared.u64 t, %1; cvt.u32.u64 %0, t; }" : "=r"(a) : "l"(p));
    return a;
}
__device__ __forceinline__ float ex2f(float x) {
    float r; asm("ex2.approx.f32 %0, %1;" : "=f"(r) : "f"(x)); return r;
}
__device__ __forceinline__ void cp16(uint32_t dst, const void* src) {
    asm volatile("cp.async.cg.shared.global [%0], [%1], 16;" :: "r"(dst), "l"(src));
}
__device__ __forceinline__ void cp_commit() {
    asm volatile("cp.async.commit_group;" ::: "memory");
}
template <int N>
__device__ __forceinline__ void cp_wait() {
    asm volatile("cp.async.wait_group %0;" :: "n"(N) : "memory");
}
__device__ __forceinline__ void ldmx4(uint32_t* r, uint32_t addr) {
    asm volatile("ldmatrix.sync.aligned.m8n8.x4.shared.b16 {%0,%1,%2,%3}, [%4];"
                 : "=r"(r[0]), "=r"(r[1]), "=r"(r[2]), "=r"(r[3]) : "r"(addr));
}
// D = A*B + C   (separate C operand: free bias / free zero-init)
__device__ __forceinline__ void mma_bf16_c(float& d0, float& d1, float& d2, float& d3,
                                           uint32_t a0, uint32_t a1, uint32_t a2, uint32_t a3,
                                           uint32_t b0, uint32_t b1,
                                           float c0, float c1, float c2, float c3) {
    asm volatile(
        "mma.sync.aligned.m16n8k16.row.col.f32.bf16.bf16.f32 "
        "{%0,%1,%2,%3}, {%4,%5,%6,%7}, {%8,%9}, {%10,%11,%12,%13};"
        : "=f"(d0), "=f"(d1), "=f"(d2), "=f"(d3)
        : "r"(a0), "r"(a1), "r"(a2), "r"(a3), "r"(b0), "r"(b1),
          "f"(c0), "f"(c1), "f"(c2), "f"(c3));
}
// D = A*B + D   (accumulate)
__device__ __forceinline__ void mma_bf16(float& d0, float& d1, float& d2, float& d3,
                                         uint32_t a0, uint32_t a1, uint32_t a2, uint32_t a3,
                                         uint32_t b0, uint32_t b1) {
    asm volatile(
        "mma.sync.aligned.m16n8k16.row.col.f32.bf16.bf16.f32 "
        "{%0,%1,%2,%3}, {%4,%5,%6,%7}, {%8,%9}, {%0,%1,%2,%3};"
        : "+f"(d0), "+f"(d1), "+f"(d2), "+f"(d3)
        : "r"(a0), "r"(a1), "r"(a2), "r"(a3), "r"(b0), "r"(b1));
}
__device__ __forceinline__ uint32_t pack_bf2(float a0, float a1) {
    __nv_bfloat162 t(__float2bfloat16(a0), __float2bfloat16(a1));
    return *reinterpret_cast<uint32_t*>(&t);
}

// ---------------- prep: warp per center ----------------
__global__ void prep_kernel(const float* __restrict__ centers,
                            const float* __restrict__ alphas,
                            const float* __restrict__ sigma) {
    const int m  = (blockIdx.x * blockDim.x + threadIdx.x) >> 5;
    const int ln = threadIdx.x & 31;
    if (m >= M_CENT) return;
    const float g = sigma[0];
    const float c = sqrtf(1.44269504088896340736f / (g * g));   // sqrt(log2e)/g
    float v = centers[m * D_DIM + ln] * c;
    __nv_bfloat16 hi = __float2bfloat16(v);
    __nv_bfloat16 lo = __float2bfloat16(v - __bfloat162float(hi));
    g_B[m * 64 + ln]      = hi;
    g_B[m * 64 + 32 + ln] = lo;
    float y2 = v * v;
#pragma unroll
    for (int o = 16; o; o >>= 1) y2 += __shfl_xor_sync(0xFFFFFFFFu, y2, o);
    if (ln == 0) g_ya[m] = make_float2(-0.5f * y2, alphas[m]);
}

// ---------------- B tile loader: tile T -> ring slot ----------------
__device__ __forceinline__ void load_btile(uint32_t sb, int slot, int T, int tid) {
    const int split = T & (NSPLIT - 1);
    const char* src = reinterpret_cast<const char*>(g_B) + (size_t)split * NTILE * 128;
    const uint32_t bd = sb + slot * SLOT;
#pragma unroll
    for (int i = 0; i < 4; i++) {
        int idx = tid + i * BLOCK;          // 0..1023 16B chunks (8 per center)
        int cc = idx >> 3, rr = idx & 7;
        cp16(bd + cc * BSTRIDE + rr * 16, src + idx * 16);
    }
    if (tid < 64) {
        const char* ys = reinterpret_cast<const char*>(g_ya + split * NTILE);
        cp16(bd + SLOT_B + tid * 16, ys + tid * 16);
    }
}

// ---------------- main kernel: persistent, 4 CTAs/SM, bias-in-C ----------------
__global__ void __launch_bounds__(BLOCK, 4)
rbf_main(const float* __restrict__ X,
         const float* __restrict__ sigma) {
    extern __shared__ char smem[];
    const uint32_t sb = smem_u32(smem);
    const int tid  = threadIdx.x;
    const int w    = tid >> 5;
    const int ln   = tid & 31;
    const int gID  = ln >> 2;
    const int qid  = ln & 3;
    const int row0 = w * 16 + gID;      // CTA-local rows: row0, row0+8
    const int row1 = row0 + 8;

    const float g = __ldg(sigma);
    const float c = sqrtf(1.44269504088896340736f / (g * g));

    const int cta = blockIdx.x;
    const int loT = (int)(((long long)cta * TOTTILES) / NCTAS);
    const int hiT = (int)(((long long)(cta + 1) * TOTTILES) / NCTAS);
    const int n   = hiT - loT;

    load_btile(sb, 0, loT, tid);
    cp_commit();
    if (n > 1) load_btile(sb, 1, loT + 1, tid);
    cp_commit();

    const uint32_t blane = (uint32_t)((ln & 7) * BSTRIDE + (ln >> 3) * 16);

    uint32_t af[4][4];
    float ex0 = 1.f, ex1 = 1.f;
    int curRb = -1;

    for (int i = 0; i < n; i++) {
        const int T  = loT + i;
        const int rb = T >> 5;

        cp_wait<1>();
        __syncthreads();

        // ---- A fragments straight from global X (registers only) ----
        if (rb != curRb) {
            curRb = rb;
            const float* r0p = X + ((size_t)rb * ROWS_CTA + row0) * D_DIM + qid * 2;
            const float* r1p = X + ((size_t)rb * ROWS_CTA + row1) * D_DIM + qid * 2;
            float s0 = 0.f, s1 = 0.f;
#pragma unroll
            for (int j = 0; j < 4; j++) {                 // cols 2qid + 8j
                float2 v0 = *reinterpret_cast<const float2*>(r0p + j * 8);
                float2 v1 = *reinterpret_cast<const float2*>(r1p + j * 8);
                v0.x *= c; v0.y *= c; v1.x *= c; v1.y *= c;
                s0 += v0.x * v0.x + v0.y * v0.y;
                s1 += v1.x * v1.x + v1.y * v1.y;
                const int s = j >> 1;
                const int h = (j & 1) << 1;
                float h0x = __bfloat162float(__float2bfloat16(v0.x));
                float h0y = __bfloat162float(__float2bfloat16(v0.y));
                float h1x = __bfloat162float(__float2bfloat16(v1.x));
                float h1y = __bfloat162float(__float2bfloat16(v1.y));
                af[s][h + 0] = pack_bf2(v0.x, v0.y);
                af[s][h + 1] = pack_bf2(v1.x, v1.y);
                af[2 + s][h + 0] = pack_bf2(v0.x - h0x, v0.y - h0y);
                af[2 + s][h + 1] = pack_bf2(v1.x - h1x, v1.y - h1y);
            }
            s0 += __shfl_xor_sync(0xFFFFFFFFu, s0, 1);
            s0 += __shfl_xor_sync(0xFFFFFFFFu, s0, 2);
            s1 += __shfl_xor_sync(0xFFFFFFFFu, s1, 1);
            s1 += __shfl_xor_sync(0xFFFFFFFFu, s1, 2);
            ex0 = ex2f(-0.5f * s0);
            ex1 = ex2f(-0.5f * s1);
        }

        // ---- consume tile i from slot i&1 ----
        const uint32_t Bb  = sb + (i & 1) * SLOT + blane;
        const char*    yab = smem + (i & 1) * SLOT + SLOT_B;

        float acc0 = 0.f, acc1 = 0.f;
#pragma unroll
        for (int gi = 0; gi < NTILE / 8; gi++) {
            const uint32_t gb = Bb + gi * (8 * BSTRIDE);
            // bias (-0.5||y||^2) and alpha for the 2 columns this thread owns
            float4 ya = *reinterpret_cast<const float4*>(yab + gi * 64 + qid * 16);
            uint32_t p[4], r[4];
            ldmx4(p, gb);          // hi k0-31
            ldmx4(r, gb + 64);     // lo k0-31

            float dA0, dA1, dA2, dA3;   // hi-chain, C = bias
            float dB0, dB1, dB2, dB3;   // lo-chain, C = 0
            // x.y ~= xh*yh + xl*yh + xh*yl   (K_eff = 96)
            mma_bf16_c(dA0,dA1,dA2,dA3, af[0][0],af[0][1],af[0][2],af[0][3], p[0],p[1],
                       ya.x, ya.z, ya.x, ya.z);
            mma_bf16_c(dB0,dB1,dB2,dB3, af[2][0],af[2][1],af[2][2],af[2][3], p[0],p[1],
                       0.f, 0.f, 0.f, 0.f);
            mma_bf16(dA0,dA1,dA2,dA3, af[1][0],af[1][1],af[1][2],af[1][3], p[2],p[3]);
            mma_bf16(dB0,dB1,dB2,dB3, af[3][0],af[3][1],af[3][2],af[3][3], p[2],p[3]);
            mma_bf16(dA0,dA1,dA2,dA3, af[0][0],af[0][1],af[0][2],af[0][3], r[0],r[1]);
            mma_bf16(dB0,dB1,dB2,dB3, af[1][0],af[1][1],af[1][2],af[1][3], r[2],r[3]);

            acc0 = fmaf(ex2f(dA0 + dB0), ya.y, acc0);
            acc0 = fmaf(ex2f(dA1 + dB1), ya.w, acc0);
            acc1 = fmaf(ex2f(dA2 + dB2), ya.y, acc1);
            acc1 = fmaf(ex2f(dA3 + dB3), ya.w, acc1);
        }

        __syncthreads();
        if (i + 2 < n) load_btile(sb, i & 1, T + 2, tid);
        cp_commit();

        acc0 += __shfl_xor_sync(0xFFFFFFFFu, acc0, 1);
        acc0 += __shfl_xor_sync(0xFFFFFFFFu, acc0, 2);
        acc1 += __shfl_xor_sync(0xFFFFFFFFu, acc1, 1);
        acc1 += __shfl_xor_sync(0xFFFFFFFFu, acc1, 2);
        if (qid == 0) {
            float* dst = g_part + (size_t)(T & (NSPLIT - 1)) * N_ROWS + rb * ROWS_CTA;
            dst[row0] = acc0 * ex0;
            dst[row1] = acc1 * ex1;
        }
    }
}

// ---------------- final reduce over 32 splits ----------------
__global__ void reduce_kernel(float* __restrict__ out) {
    const int nidx = blockIdx.x * blockDim.x + threadIdx.x;
    float s = 0.f;
#pragma unroll
    for (int i = 0; i < NSPLIT; i++) s += g_part[(size_t)i * N_ROWS + nidx];
    out[nidx] = s;
}

// ---------------- launch ----------------
extern "C" void kernel_launch(void* const* d_in, const int* in_sizes, int n_in,
                              void* d_out, int out_size) {
    const float* X       = (const float*)d_in[0];
    const float* centers = (const float*)d_in[1];
    const float* alphas  = (const float*)d_in[2];
    const float* sigma   = (const float*)d_in[3];
    float* out = (float*)d_out;

    cudaFuncSetAttribute(rbf_main, cudaFuncAttributeMaxDynamicSharedMemorySize, SMEM_TOT);

    prep_kernel<<<M_CENT / 8, 256>>>(centers, alphas, sigma);
    rbf_main<<<NCTAS, BLOCK, SMEM_TOT>>>(X, sigma);
    reduce_kernel<<<N_ROWS / 256, 256>>>(out);
}